// round 14
// baseline (speedup 1.0000x reference)
#include <cuda_runtime.h>
#include <cstdint>

// Problem constants (FrustumPooling_721554506291)
#define Bb 2
#define Nn 4
#define Dd 48
#define Hh 28
#define Ww 60
#define Cc 64
#define NX 192
#define NY 192
#define PLANE (NY*NX)                  // 36864
#define OUT_ELEMS (Bb*Cc*PLANE)        // 4,718,592 floats
#define NBLOCKS (Bb*Dd*Ww)             // 5760 columns, one block each
#define NPAIRS (Nn*Hh)                 // 112 (n,h) vectors per column
#define NHW 16                         // half-warps per block
#define PER_HW (NPAIRS/NHW)            // 7 pairs per half-warp
#define NSLOT (NHW*2)                  // 32 merge slots (slow path)

static_assert(NPAIRS % NHW == 0, "pairs must split across half-warps");

// Per-(b,n): combine[9] followed by trans[3] — computed once in zero kernel.
__device__ float g_combine[Bb*Nn*12];

// ---------------------------------------------------------------------------
// Zero output + (block 0) compute combine = rots @ inv(K).
// ---------------------------------------------------------------------------
__global__ void zero_setup_kernel(float4* __restrict__ o,
                                  const float* __restrict__ intr,
                                  const float* __restrict__ pose)
{
    int i = blockIdx.x * blockDim.x + threadIdx.x;
    if (i < OUT_ELEMS/4)
        o[i] = make_float4(0.f, 0.f, 0.f, 0.f);

    if (blockIdx.x == 0 && threadIdx.x < Bb*Nn) {
        int t = threadIdx.x;
        const float* K = intr + t*9;
        const float* P = pose + t*16;

        float a=K[0], b=K[1], c=K[2];
        float d=K[3], e=K[4], f=K[5];
        float g=K[6], h=K[7], ii=K[8];
        float A0 =  (e*ii - f*h);
        float A1 = -(d*ii - f*g);
        float A2 =  (d*h  - e*g);
        float det = a*A0 + b*A1 + c*A2;
        float id  = 1.0f / det;
        float inv[9];
        inv[0] = A0*id;           inv[1] = (c*h - b*ii)*id; inv[2] = (b*f - c*e)*id;
        inv[3] = A1*id;           inv[4] = (a*ii - c*g)*id; inv[5] = (c*d - a*f)*id;
        inv[6] = A2*id;           inv[7] = (b*g - a*h)*id;  inv[8] = (a*e - b*d)*id;

        float* out = g_combine + t*12;
        #pragma unroll
        for (int r = 0; r < 3; r++) {
            #pragma unroll
            for (int col = 0; col < 3; col++) {
                out[r*3+col] = P[r*4+0]*inv[0*3+col]
                             + P[r*4+1]*inv[1*3+col]
                             + P[r*4+2]*inv[2*3+col];
            }
            out[9+r] = P[r*4+3];
        }
    }
}

__device__ __forceinline__ void red1(float* addr, float v)
{
    asm volatile("red.global.add.f32 [%0], %1;" :: "l"(addr), "f"(v) : "memory");
}

__device__ __forceinline__ void acc4(float4& a, const float4& b)
{
    a.x += b.x; a.y += b.y; a.z += b.z; a.w += b.w;
}

__device__ __forceinline__ void flush4(float* __restrict__ outp, float4 a)
{
    red1(outp,           a.x);
    red1(outp +   PLANE, a.y);
    red1(outp + 2*PLANE, a.z);
    red1(outp + 3*PLANE, a.w);
}

// ---------------------------------------------------------------------------
// Column scatter, block-per-(b,d,w):
//   Phase A: 112 threads compute cell per (n,h) pair; compact kept list +
//            all-same-cell detection via smem atomics (generic).
//   Fast-full path (all NPAIRS kept, one cell): x offsets computed
//            arithmetically (no LDS dependency), 7 fully-unrolled __ldcs
//            LDG.128 per half-warp -> front-batched MLP=7.
//   Fast-partial path: strided compact-list loop with 4 accumulators.
//   Slow path: 2-slot merge + generic dedup (any geometry).
// ---------------------------------------------------------------------------
__global__ void __launch_bounds__(256)
scatter_kernel(const float* __restrict__ x, float* __restrict__ out)
{
    __shared__ float s_cm[Bb*Nn*12];
    __shared__ int   s_cell[NPAIRS];        // cell per pair (-1 rejected)
    __shared__ int   s_pxoff[NPAIRS];       // x offset per pair (slow path)
    __shared__ int   s_cxoff[NPAIRS];       // compact kept x offsets
    __shared__ int   s_run[NSLOT];
    __shared__ float s_acc[NSLOT][Cc];
    __shared__ int   s_cnt, s_same, s_first;

    int tid = threadIdx.x;
    if (tid < Bb*Nn*12) s_cm[tid] = g_combine[tid];
    if (tid == 0) { s_cnt = 0; s_same = 1; s_first = -1; }
    __syncthreads();

    // ---- column decode ----
    int gcol = blockIdx.x;
    int w  = gcol % Ww;  int t2 = gcol / Ww;
    int d  = t2 % Dd;
    int b  = t2 / Dd;

    float u  = (float)w * (479.0f/59.0f);
    float df = 2.0f + (float)d;
    float ud = u * df;

    // ---- Phase A: one thread per (n,h) pair ----
    if (tid < NPAIRS) {
        int n = tid / Hh;
        int h = tid - n*Hh;

        const float* cm = s_cm + (b*Nn + n)*12;
        float vd = ((float)h * (223.0f/27.0f)) * df;
        float g0 = cm[0]*ud + cm[2]*df + cm[9]  + cm[1]*vd;
        float g1 = cm[3]*ud + cm[5]*df + cm[10] + cm[4]*vd;
        float g2 = cm[6]*ud + cm[8]*df + cm[11] + cm[7]*vd;

        int gx = (int)(g0 * 4.0f + 96.0f);   // trunc-toward-zero == astype(int32)
        int gy = (int)(g1 * 4.0f + 96.0f);
        int gz = (int)((g2 + 10.0f) / 20.0f);

        bool kept = ((unsigned)gx < NX) && ((unsigned)gy < NY) && (gz == 0);
        int cell = kept ? (gy*NX + gx) : -1;
        int xoff = (n*(Dd*Hh*Ww) + h*Ww) * Cc;
        s_cell[tid]  = cell;
        s_pxoff[tid] = xoff;
        if (kept) {
            int old = atomicCAS(&s_first, -1, cell);
            if (old != -1 && old != cell) s_same = 0;
            int p = atomicAdd(&s_cnt, 1);
            s_cxoff[p] = xoff;
        }
    }
    __syncthreads();

    int cnt = s_cnt;
    if (cnt == 0) return;                 // empty column (uniform exit)

    int hw = tid >> 4;                    // 0..15
    int l4 = (tid & 15) * 4;              // channel base

    const float* xcol = x + ((size_t)(b*Nn)*Dd + d) * (Hh*Ww*Cc)
                          + w*Cc + l4;

    if (s_same) {
        float4 a0 = make_float4(0.f,0.f,0.f,0.f);
        float4 a1 = make_float4(0.f,0.f,0.f,0.f);
        float4 a2 = make_float4(0.f,0.f,0.f,0.f);
        float4 a3 = make_float4(0.f,0.f,0.f,0.f);

        if (cnt == NPAIRS) {
            // fully-kept: offsets are arithmetic in the pair index ->
            // 7 independent __ldcs loads, all issued before the adds
            #pragma unroll
            for (int j = 0; j < PER_HW; j++) {
                int idx = hw*PER_HW + j;
                int n = idx / Hh;
                int h = idx - n*Hh;
                float4 v = __ldcs(reinterpret_cast<const float4*>(
                    xcol + (n*(Dd*Hh*Ww) + h*Ww)*Cc));
                if ((j & 3) == 0) acc4(a0, v);
                else if ((j & 3) == 1) acc4(a1, v);
                else if ((j & 3) == 2) acc4(a2, v);
                else acc4(a3, v);
            }
        } else {
            // partial: strided compact list, 4 accumulators for MLP
            int i = hw;
            for (; i + 3*NHW < cnt; i += 4*NHW) {
                float4 v0 = __ldcs(reinterpret_cast<const float4*>(xcol + s_cxoff[i]));
                float4 v1 = __ldcs(reinterpret_cast<const float4*>(xcol + s_cxoff[i+NHW]));
                float4 v2 = __ldcs(reinterpret_cast<const float4*>(xcol + s_cxoff[i+2*NHW]));
                float4 v3 = __ldcs(reinterpret_cast<const float4*>(xcol + s_cxoff[i+3*NHW]));
                acc4(a0, v0); acc4(a1, v1); acc4(a2, v2); acc4(a3, v3);
            }
            for (; i < cnt; i += NHW)
                acc4(a0, __ldcs(reinterpret_cast<const float4*>(xcol + s_cxoff[i])));
        }
        acc4(a0, a1); acc4(a2, a3); acc4(a0, a2);

        s_acc[hw][l4]   = a0.x;  s_acc[hw][l4+1] = a0.y;
        s_acc[hw][l4+2] = a0.z;  s_acc[hw][l4+3] = a0.w;
        __syncthreads();

        if (tid < Cc) {
            float sum = 0.f;
            #pragma unroll
            for (int e = 0; e < NHW; e++) sum += s_acc[e][tid];
            red1(out + ((size_t)b*Cc + tid)*PLANE + s_first, sum);
        }
        return;
    }

    // ---- slow path: 2-slot merge per half-warp + generic dedup ----
    float* outbase = out + ((size_t)b*Cc + l4) * PLANE;

    int    r0 = -1, r1 = -1;
    float4 a0, a1;
    #pragma unroll
    for (int j = 0; j < PER_HW; j++) {
        int idx  = hw*PER_HW + j;
        int cell = s_cell[idx];
        if (cell >= 0) {
            float4 val = __ldcs(reinterpret_cast<const float4*>(xcol + s_pxoff[idx]));
            if      (cell == r0) acc4(a0, val);
            else if (cell == r1) acc4(a1, val);
            else if (r0 < 0)     { r0 = cell; a0 = val; }
            else if (r1 < 0)     { r1 = cell; a1 = val; }
            else {               // spill oldest (rare)
                flush4(outbase + r0, a0);
                r0 = cell; a0 = val;
            }
        }
    }

    if ((tid & 15) == 0) {
        s_run[hw*2]   = r0;
        s_run[hw*2+1] = r1;
    }
    s_acc[hw*2][l4]     = a0.x;  s_acc[hw*2][l4+1]   = a0.y;
    s_acc[hw*2][l4+2]   = a0.z;  s_acc[hw*2][l4+3]   = a0.w;
    s_acc[hw*2+1][l4]   = a1.x;  s_acc[hw*2+1][l4+1] = a1.y;
    s_acc[hw*2+1][l4+2] = a1.z;  s_acc[hw*2+1][l4+3] = a1.w;
    __syncthreads();

    if (tid < Cc) {
        float* outc = out + ((size_t)b*Cc + tid)*PLANE;
        for (int e = 0; e < NSLOT; e++) {
            int r = s_run[e];
            if (r < 0) continue;
            bool first = true;
            for (int f = 0; f < e; f++)
                if (s_run[f] == r) { first = false; break; }
            if (!first) continue;
            float sum = s_acc[e][tid];
            for (int f = e+1; f < NSLOT; f++)
                if (s_run[f] == r) sum += s_acc[f][tid];
            red1(outc + r, sum);
        }
    }
}

// ---------------------------------------------------------------------------
extern "C" void kernel_launch(void* const* d_in, const int* in_sizes, int n_in,
                              void* d_out, int out_size)
{
    const float* x    = (const float*)d_in[0];
    const float* intr = (const float*)d_in[1];
    const float* pose = (const float*)d_in[2];
    float* out = (float*)d_out;

    zero_setup_kernel<<<OUT_ELEMS/4/256, 256>>>((float4*)out, intr, pose);
    scatter_kernel<<<NBLOCKS, 256>>>(x, out);
}

// round 15
// speedup vs baseline: 1.0732x; 1.0732x over previous
#include <cuda_runtime.h>
#include <cstdint>

// Problem constants (FrustumPooling_721554506291)
#define Bb 2
#define Nn 4
#define Dd 48
#define Hh 28
#define Ww 60
#define Cc 64
#define NX 192
#define NY 192
#define PLANE (NY*NX)                  // 36864
#define OUT_ELEMS (Bb*Cc*PLANE)        // 4,718,592 floats
#define NCOLS (Bb*Dd*Ww)               // 5760 columns total
#define NPAIRS (Nn*Hh)                 // 112 (n,h) vectors per column
#define NCOL 2                         // columns per block
#define NBLK (NCOLS/NCOL)              // 2880 blocks
#define NCHUNK 8                       // half-warp chunks per column
#define PER_CHUNK (NPAIRS/NCHUNK)      // 14 pairs per chunk
#define NSLOT 32                       // merge slots (2 per half-warp)

static_assert(NPAIRS % NCHUNK == 0, "chunks");
static_assert(NCOLS % NCOL == 0, "block pairing");
static_assert((Dd*Ww) % NCOL == 0, "column pairs never straddle b");

// Per-(b,n): combine[9] followed by trans[3] — computed once in zero kernel.
__device__ float g_combine[Bb*Nn*12];

// ---------------------------------------------------------------------------
// Zero output + (block 0) compute combine = rots @ inv(K).
// ---------------------------------------------------------------------------
__global__ void zero_setup_kernel(float4* __restrict__ o,
                                  const float* __restrict__ intr,
                                  const float* __restrict__ pose)
{
    int i = blockIdx.x * blockDim.x + threadIdx.x;
    if (i < OUT_ELEMS/4)
        o[i] = make_float4(0.f, 0.f, 0.f, 0.f);

    if (blockIdx.x == 0 && threadIdx.x < Bb*Nn) {
        int t = threadIdx.x;
        const float* K = intr + t*9;
        const float* P = pose + t*16;

        float a=K[0], b=K[1], c=K[2];
        float d=K[3], e=K[4], f=K[5];
        float g=K[6], h=K[7], ii=K[8];
        float A0 =  (e*ii - f*h);
        float A1 = -(d*ii - f*g);
        float A2 =  (d*h  - e*g);
        float det = a*A0 + b*A1 + c*A2;
        float id  = 1.0f / det;
        float inv[9];
        inv[0] = A0*id;           inv[1] = (c*h - b*ii)*id; inv[2] = (b*f - c*e)*id;
        inv[3] = A1*id;           inv[4] = (a*ii - c*g)*id; inv[5] = (c*d - a*f)*id;
        inv[6] = A2*id;           inv[7] = (b*g - a*h)*id;  inv[8] = (a*e - b*d)*id;

        float* out = g_combine + t*12;
        #pragma unroll
        for (int r = 0; r < 3; r++) {
            #pragma unroll
            for (int col = 0; col < 3; col++) {
                out[r*3+col] = P[r*4+0]*inv[0*3+col]
                             + P[r*4+1]*inv[1*3+col]
                             + P[r*4+2]*inv[2*3+col];
            }
            out[9+r] = P[r*4+3];
        }
    }
}

__device__ __forceinline__ void red1(float* addr, float v)
{
    asm volatile("red.global.add.f32 [%0], %1;" :: "l"(addr), "f"(v) : "memory");
}

__device__ __forceinline__ void acc4(float4& a, const float4& b)
{
    a.x += b.x; a.y += b.y; a.z += b.z; a.w += b.w;
}

__device__ __forceinline__ void flush4(float* __restrict__ outp, float4 a)
{
    red1(outp,           a.x);
    red1(outp +   PLANE, a.y);
    red1(outp + 2*PLANE, a.z);
    red1(outp + 3*PLANE, a.w);
}

// ---------------------------------------------------------------------------
// Column scatter, block-per-2-adjacent-columns:
//   Phase A: 224 threads compute cell per (col, n,h) pair; per-column compact
//            kept lists + all-same detection (generic, smem atomics).
//   Phase B: 16 half-warps; hw -> (col = hw&1, chunk = hw>>1). A warp's two
//            half-warps cover the SAME chunk for adjacent w -> 512B contiguous
//            warp loads. Full-fast path: 14 arithmetic-offset __ldcs loads,
//            front-batched. Partial: strided compact list. Slow: 2-slot merge.
//   Tail:    128 threads (64 per column): same-cell columns sum 8 primary
//            slots + ONE red/channel; otherwise generic 16-slot dedup.
// ---------------------------------------------------------------------------
__global__ void __launch_bounds__(256)
scatter_kernel(const float* __restrict__ x, float* __restrict__ out)
{
    __shared__ float s_cm[Bb*Nn*12];
    __shared__ int   s_cell[NCOL][NPAIRS];
    __shared__ int   s_pxoff[NCOL][NPAIRS];
    __shared__ int   s_cxoff[NCOL][NPAIRS];
    __shared__ int   s_run[NSLOT];
    __shared__ float s_acc[NSLOT][Cc];
    __shared__ int   s_cnt[NCOL], s_same[NCOL], s_first[NCOL];

    int tid = threadIdx.x;
    if (tid < Bb*Nn*12) s_cm[tid] = g_combine[tid];
    if (tid < NCOL) { s_cnt[tid] = 0; s_same[tid] = 1; s_first[tid] = -1; }
    __syncthreads();

    // ---- Phase A: one thread per (col, pair) ----
    if (tid < NCOL*NPAIRS) {
        int col = tid / NPAIRS;
        int p   = tid - col*NPAIRS;
        int n = p / Hh;
        int h = p - n*Hh;

        int gcol = blockIdx.x*NCOL + col;
        int w  = gcol % Ww;  int t2 = gcol / Ww;
        int d  = t2 % Dd;
        int b  = t2 / Dd;

        float u  = (float)w * (479.0f/59.0f);
        float df = 2.0f + (float)d;
        float ud = u * df;

        const float* cm = s_cm + (b*Nn + n)*12;
        float vd = ((float)h * (223.0f/27.0f)) * df;
        float g0 = cm[0]*ud + cm[2]*df + cm[9]  + cm[1]*vd;
        float g1 = cm[3]*ud + cm[5]*df + cm[10] + cm[4]*vd;
        float g2 = cm[6]*ud + cm[8]*df + cm[11] + cm[7]*vd;

        int gx = (int)(g0 * 4.0f + 96.0f);   // trunc-toward-zero == astype(int32)
        int gy = (int)(g1 * 4.0f + 96.0f);
        int gz = (int)((g2 + 10.0f) / 20.0f);

        bool kept = ((unsigned)gx < NX) && ((unsigned)gy < NY) && (gz == 0);
        int cell = kept ? (gy*NX + gx) : -1;
        int xoff = (n*(Dd*Hh*Ww) + h*Ww) * Cc;
        s_cell[col][p]  = cell;
        s_pxoff[col][p] = xoff;
        if (kept) {
            int old = atomicCAS(&s_first[col], -1, cell);
            if (old != -1 && old != cell) s_same[col] = 0;
            int q = atomicAdd(&s_cnt[col], 1);
            s_cxoff[col][q] = xoff;
        }
    }
    __syncthreads();

    if (s_cnt[0] == 0 && s_cnt[1] == 0) return;   // both columns empty

    // ---- Phase B ----
    int hw    = tid >> 4;           // 0..15
    int col   = hw & 1;
    int chunk = hw >> 1;            // 0..7
    int l4    = (tid & 15) * 4;     // channel base

    int gcol = blockIdx.x*NCOL + col;
    int w  = gcol % Ww;  int t2 = gcol / Ww;
    int d  = t2 % Dd;
    int b  = t2 / Dd;

    const float* xcol = x + ((size_t)(b*Nn)*Dd + d) * (Hh*Ww*Cc)
                          + w*Cc + l4;
    float* outbase = out + ((size_t)b*Cc + l4) * PLANE;

    int cnt = s_cnt[col];
    int slotA = 2*hw, slotB = 2*hw + 1;

    if (cnt > 0 && s_same[col]) {
        float4 a0 = make_float4(0.f,0.f,0.f,0.f);
        float4 a1 = make_float4(0.f,0.f,0.f,0.f);
        float4 a2 = make_float4(0.f,0.f,0.f,0.f);
        float4 a3 = make_float4(0.f,0.f,0.f,0.f);

        if (cnt == NPAIRS) {
            // fully-kept: arithmetic offsets, 14 front-batched loads
            #pragma unroll
            for (int j = 0; j < PER_CHUNK; j++) {
                int idx = chunk*PER_CHUNK + j;
                int n = idx / Hh;
                int h = idx - n*Hh;
                float4 v = __ldcs(reinterpret_cast<const float4*>(
                    xcol + (n*(Dd*Hh*Ww) + h*Ww)*Cc));
                if ((j & 3) == 0) acc4(a0, v);
                else if ((j & 3) == 1) acc4(a1, v);
                else if ((j & 3) == 2) acc4(a2, v);
                else acc4(a3, v);
            }
        } else {
            int i = chunk;
            for (; i + 3*NCHUNK < cnt; i += 4*NCHUNK) {
                float4 v0 = __ldcs(reinterpret_cast<const float4*>(xcol + s_cxoff[col][i]));
                float4 v1 = __ldcs(reinterpret_cast<const float4*>(xcol + s_cxoff[col][i+NCHUNK]));
                float4 v2 = __ldcs(reinterpret_cast<const float4*>(xcol + s_cxoff[col][i+2*NCHUNK]));
                float4 v3 = __ldcs(reinterpret_cast<const float4*>(xcol + s_cxoff[col][i+3*NCHUNK]));
                acc4(a0, v0); acc4(a1, v1); acc4(a2, v2); acc4(a3, v3);
            }
            for (; i < cnt; i += NCHUNK)
                acc4(a0, __ldcs(reinterpret_cast<const float4*>(xcol + s_cxoff[col][i])));
        }
        acc4(a0, a1); acc4(a2, a3); acc4(a0, a2);

        if ((tid & 15) == 0) { s_run[slotA] = s_first[col]; s_run[slotB] = -1; }
        s_acc[slotA][l4]   = a0.x;  s_acc[slotA][l4+1] = a0.y;
        s_acc[slotA][l4+2] = a0.z;  s_acc[slotA][l4+3] = a0.w;
    } else if (cnt > 0) {
        // ---- slow path: 2-slot merge over this chunk ----
        int    r0 = -1, r1 = -1;
        float4 a0, a1;
        #pragma unroll
        for (int j = 0; j < PER_CHUNK; j++) {
            int idx  = chunk*PER_CHUNK + j;
            int cell = s_cell[col][idx];
            if (cell >= 0) {
                float4 val = __ldcs(reinterpret_cast<const float4*>(
                    xcol + s_pxoff[col][idx]));
                if      (cell == r0) acc4(a0, val);
                else if (cell == r1) acc4(a1, val);
                else if (r0 < 0)     { r0 = cell; a0 = val; }
                else if (r1 < 0)     { r1 = cell; a1 = val; }
                else {               // spill oldest (rare)
                    flush4(outbase + r0, a0);
                    r0 = cell; a0 = val;
                }
            }
        }
        if ((tid & 15) == 0) { s_run[slotA] = r0; s_run[slotB] = r1; }
        s_acc[slotA][l4]   = a0.x;  s_acc[slotA][l4+1] = a0.y;
        s_acc[slotA][l4+2] = a0.z;  s_acc[slotA][l4+3] = a0.w;
        s_acc[slotB][l4]   = a1.x;  s_acc[slotB][l4+1] = a1.y;
        s_acc[slotB][l4+2] = a1.z;  s_acc[slotB][l4+3] = a1.w;
    } else {
        if ((tid & 15) == 0) { s_run[slotA] = -1; s_run[slotB] = -1; }
    }
    __syncthreads();

    // ---- tail: 64 threads per column ----
    if (tid < NCOL*Cc) {
        int tcol = tid >> 6;          // 0/1
        int c    = tid & (Cc-1);
        if (s_cnt[tcol] == 0) return;

        int gc2 = blockIdx.x*NCOL + tcol;
        int b2  = gc2 / (Dd*Ww);
        float* outc = out + ((size_t)b2*Cc + c) * PLANE;

        if (s_same[tcol]) {
            float sum = 0.f;
            #pragma unroll
            for (int k = 0; k < NCHUNK; k++)
                sum += s_acc[2*(tcol + 2*k)][c];
            red1(outc + s_first[tcol], sum);
        } else {
            // generic dedup over this column's 16 slots
            #pragma unroll 1
            for (int ke = 0; ke < 2*NCHUNK; ke++) {
                int e = 2*(tcol + 2*(ke >> 1)) + (ke & 1);
                int r = s_run[e];
                if (r < 0) continue;
                bool first = true;
                for (int kf = 0; kf < ke; kf++) {
                    int f = 2*(tcol + 2*(kf >> 1)) + (kf & 1);
                    if (s_run[f] == r) { first = false; break; }
                }
                if (!first) continue;
                float sum = s_acc[e][c];
                for (int kf = ke+1; kf < 2*NCHUNK; kf++) {
                    int f = 2*(tcol + 2*(kf >> 1)) + (kf & 1);
                    if (s_run[f] == r) sum += s_acc[f][c];
                }
                red1(outc + r, sum);
            }
        }
    }
}

// ---------------------------------------------------------------------------
extern "C" void kernel_launch(void* const* d_in, const int* in_sizes, int n_in,
                              void* d_out, int out_size)
{
    const float* x    = (const float*)d_in[0];
    const float* intr = (const float*)d_in[1];
    const float* pose = (const float*)d_in[2];
    float* out = (float*)d_out;

    zero_setup_kernel<<<OUT_ELEMS/4/256, 256>>>((float4*)out, intr, pose);
    scatter_kernel<<<NBLK, 256>>>(x, out);
}